// round 10
// baseline (speedup 1.0000x reference)
#include <cuda_runtime.h>
#include <math.h>

#define B_TOT   4096
#define SRC_LEN 128
#define IN_DIM  16
#define HD      64
#define G3      192
#define SEQ     100
#define ROWS    32
#define NT      512

typedef unsigned long long u64;

// packed fp32 FMA: d = a*b + c componentwise (Blackwell FFMA2 pipe, full fp32)
__device__ __forceinline__ u64 fma2(u64 a, u64 b, u64 c) {
    u64 d;
    asm("fma.rn.f32x2 %0, %1, %2, %3;" : "=l"(d) : "l"(a), "l"(b), "l"(c));
    return d;
}
__device__ __forceinline__ float2 unpack2(u64 v) {
    float2 f;
    asm("mov.b64 {%0, %1}, %2;" : "=f"(f.x), "=f"(f.y) : "l"(v));
    return f;
}
__device__ __forceinline__ u64 pack2(float lo, float hi) {
    u64 d;
    asm("mov.b64 %0, {%1, %2};" : "=l"(d) : "f"(lo), "f"(hi));
    return d;
}
__device__ __forceinline__ u64 ld64s(const float* p) {
    return *reinterpret_cast<const u64*>(p);
}
// fast gates. __fdividef returns 0 for |denominator| > 2^126, so exp-overflow
// saturates correctly: sigmoid -> 0, tanh -> 1 (and e->0 gives tanh -> -1).
__device__ __forceinline__ float sigm(float s) {
    return __fdividef(1.f, 1.f + __expf(-s));
}
__device__ __forceinline__ float tanh_fast(float x) {
    float e = __expf(2.f * x);
    return 1.f - __fdividef(2.f, e + 1.f);
}
// packed dot-product accumulate over n pair-of-pairs (4 floats per iter),
// both pointers 16B-aligned; accumulation order identical to the scalar-pair loop
template<int NQ>
__device__ __forceinline__ u64 dot_q(const float* __restrict__ a,
                                     const float* __restrict__ b, u64 acc2)
{
#pragma unroll
    for (int i = 0; i < NQ; ++i) {
        ulonglong2 av = *reinterpret_cast<const ulonglong2*>(a + 4 * i);
        ulonglong2 bv = *reinterpret_cast<const ulonglong2*>(b + 4 * i);
        acc2 = fma2(av.x, bv.x, acc2);
        acc2 = fma2(av.y, bv.y, acc2);
    }
    return acc2;
}

// ---- shared memory layout (float offsets) ----
#define OFF_EWIH 0        // [16][192] enc Wih^T
#define OFF_EWHH 3072     // [64][192] enc Whh^T
#define OFF_DWIH 15360    // [16][192]
#define OFF_DWHH 18432    // [64][192]
#define OFF_EBIH 30720    // [192]
#define OFF_EBHH 30912
#define OFF_DBIH 31104
#define OFF_DBHH 31296
#define OFF_OUTW 31488    // [16][64]  (16B-aligned rows)
#define OFF_OUTB 32512    // [16]
#define OFF_EMBW 32528    // [16][4]
#define OFF_EMBB 32592    // [16]
#define OFF_W1   32608    // [128][16]  rows 0..63 = mean head, 64..127 = cov head
#define OFF_B1   34656    // [128]
#define OFF_W2   34784    // [14][64]   rows 0..3 = mean head, 4..13 = cov head
#define OFF_B2   35680    // [14] (ends 35694, pad 2)
#define OFF_HD   35696    // 2 x [64][32 dup-pairs] h double-buffered (8192)
#define OFF_XS   43888    // 2 x [16][32 dup-pairs] input            (2048)
#define OFF_HROW 45936    // [32][68] h row-major, 16B-aligned rows  (2176)
#define OFF_OROW 48112    // [32][20] o row-major, 16B-aligned rows  (640)
#define OFF_HH   48752    // [32][132] head hidden, 16B-aligned rows (4224)
#define SMEM_FLOATS 52976
#define SMEM_BYTES  (SMEM_FLOATS * 4)

#define HROW_S 68
#define OROW_S 20
#define HH_S   132

// Fused GRU matmul + gate, all in registers. 512-thread tiling:
// rows {2rg, 2rg+1} (rg = tid&15) — ADJACENT rows, so both rows' dup-pairs
// sit in one 16B chunk => single LDS.128 per activation per k.
// Hidden-unit pair j0 = 2*jg (jg = tid>>4).
// Accumulators are SEEDED with packed biases (bp[0]=b_r, bp[1]=b_z combined
// ih+hh pairs; bp[2]=b_in, bp[3]=b_hn), removing all post-loop bias adds.
// Reads h/x from CURRENT buffers only; caller writes NEXT buffers
// (double-buffered => no barrier inside the step).
__device__ __forceinline__ void gru_step(
    const float* __restrict__ WihT, const float* __restrict__ WhhT,
    const float* __restrict__ Xd,   const float* __restrict__ Hd,
    const u64* __restrict__ bp,
    int rg, int jg, float hnew[2][2])
{
    u64 ir[2], iz[2], inn[2], hr[2], hz[2], hn[2];
#pragma unroll
    for (int r = 0; r < 2; ++r) {
        ir[r] = bp[0]; iz[r] = bp[1]; inn[r] = bp[2]; hn[r] = bp[3];
        hr[r] = 0ull;  hz[r] = 0ull;
    }
    const int j0 = 2 * jg;
    const int ro4 = 4 * rg;   // float offset of rows {2rg, 2rg+1} dup-pairs

#pragma unroll 4
    for (int k = 0; k < IN_DIM; ++k) {
        // one 16B load = dup-pairs of both rows: .x = (x0,x0), .y = (x1,x1)
        ulonglong2 xq = *reinterpret_cast<const ulonglong2*>(&Xd[k * 64 + ro4]);
        const float* wrow = WihT + k * G3 + j0;
        u64 wr = ld64s(wrow), wz = ld64s(wrow + 64), wn = ld64s(wrow + 128);
        ir[0]  = fma2(xq.x, wr, ir[0]);   ir[1]  = fma2(xq.y, wr, ir[1]);
        iz[0]  = fma2(xq.x, wz, iz[0]);   iz[1]  = fma2(xq.y, wz, iz[1]);
        inn[0] = fma2(xq.x, wn, inn[0]);  inn[1] = fma2(xq.y, wn, inn[1]);
    }

#pragma unroll 8
    for (int k = 0; k < HD; ++k) {
        ulonglong2 hq = *reinterpret_cast<const ulonglong2*>(&Hd[k * 64 + ro4]);
        const float* wrow = WhhT + k * G3 + j0;
        u64 wr = ld64s(wrow), wz = ld64s(wrow + 64), wn = ld64s(wrow + 128);
        hr[0] = fma2(hq.x, wr, hr[0]);    hr[1] = fma2(hq.y, wr, hr[1]);
        hz[0] = fma2(hq.x, wz, hz[0]);    hz[1] = fma2(hq.y, wz, hz[1]);
        hn[0] = fma2(hq.x, wn, hn[0]);    hn[1] = fma2(hq.y, wn, hn[1]);
    }

    // old h for units j0, j0+1 at both rows: one LDS.128 per unit
    float4 hold0 = *reinterpret_cast<const float4*>(&Hd[j0 * 64 + ro4]);
    float4 hold1 = *reinterpret_cast<const float4*>(&Hd[(j0 + 1) * 64 + ro4]);
    float holdv[2][2] = { {hold0.x, hold1.x}, {hold0.z, hold1.z} };

#pragma unroll
    for (int r = 0; r < 2; ++r) {
        float2 fir = unpack2(ir[r]),  fiz = unpack2(iz[r]),  fin = unpack2(inn[r]);
        float2 fhr = unpack2(hr[r]),  fhz = unpack2(hz[r]),  fhn = unpack2(hn[r]);
#pragma unroll
        for (int h = 0; h < 2; ++h) {
            float vir = h ? fir.y : fir.x, vhr = h ? fhr.y : fhr.x;
            float viz = h ? fiz.y : fiz.x, vhz = h ? fhz.y : fhz.x;
            float vin = h ? fin.y : fin.x, vhn = h ? fhn.y : fhn.x;
            float rr = sigm(vir + vhr);                  // biases pre-seeded
            float zz = sigm(viz + vhz);
            float nn = tanh_fast(vin + rr * vhn);
            hnew[r][h] = (1.f - zz) * nn + zz * holdv[r][h];
        }
    }
}

// store hnew into the dup-pair NEXT buffer: one STS.128 per unit
__device__ __forceinline__ void store_h_dup(
    float* __restrict__ hdn, int rg, int j0, const float hnew[2][2])
{
    const int ro4 = 4 * rg;
    *reinterpret_cast<float4*>(&hdn[j0 * 64 + ro4])
        = make_float4(hnew[0][0], hnew[0][0], hnew[1][0], hnew[1][0]);
    *reinterpret_cast<float4*>(&hdn[(j0 + 1) * 64 + ro4])
        = make_float4(hnew[0][1], hnew[0][1], hnew[1][1], hnew[1][1]);
}

__global__ void __launch_bounds__(NT)
seq2seq_kernel(
    const float* __restrict__ x,       const float* __restrict__ trg,
    const float* __restrict__ enc_Wih, const float* __restrict__ enc_bih,
    const float* __restrict__ enc_Whh, const float* __restrict__ enc_bhh,
    const float* __restrict__ dec_Wih, const float* __restrict__ dec_bih,
    const float* __restrict__ dec_Whh, const float* __restrict__ dec_bhh,
    const float* __restrict__ out_W,   const float* __restrict__ out_b,
    const float* __restrict__ emb_W,   const float* __restrict__ emb_b,
    const float* __restrict__ mh_W1,   const float* __restrict__ mh_b1,
    const float* __restrict__ mh_W2,   const float* __restrict__ mh_b2,
    const float* __restrict__ ch_W1,   const float* __restrict__ ch_b1,
    const float* __restrict__ ch_W2,   const float* __restrict__ ch_b2,
    float* __restrict__ d_out)
{
    extern __shared__ float sm[];
    const int tid = threadIdx.x;
    const int b0  = blockIdx.x * ROWS;

    // ---- load + transpose weights into smem ----
    for (int i = tid; i < 3072; i += NT) {
        int g = i >> 4, k = i & 15;
        sm[OFF_EWIH + k * G3 + g] = enc_Wih[i];
        sm[OFF_DWIH + k * G3 + g] = dec_Wih[i];
    }
    for (int i = tid; i < 12288; i += NT) {
        int g = i >> 6, k = i & 63;
        sm[OFF_EWHH + k * G3 + g] = enc_Whh[i];
        sm[OFF_DWHH + k * G3 + g] = dec_Whh[i];
    }
    for (int i = tid; i < G3; i += NT) {
        sm[OFF_EBIH + i] = enc_bih[i];
        sm[OFF_EBHH + i] = enc_bhh[i];
        sm[OFF_DBIH + i] = dec_bih[i];
        sm[OFF_DBHH + i] = dec_bhh[i];
    }
    // head weights combined: W1 = [mh_W1 ; ch_W1], W2 = [mh_W2 ; ch_W2]
    for (int i = tid; i < 1024; i += NT) {
        sm[OFF_OUTW + i]      = out_W[i];
        sm[OFF_W1 + i]        = mh_W1[i];
        sm[OFF_W1 + 1024 + i] = ch_W1[i];
    }
    for (int i = tid; i < 640; i += NT) sm[OFF_W2 + 256 + i] = ch_W2[i];
    for (int i = tid; i < 256; i += NT) sm[OFF_W2 + i] = mh_W2[i];
    if (tid < 16) { sm[OFF_OUTB + tid] = out_b[tid]; sm[OFF_EMBB + tid] = emb_b[tid]; }
    if (tid < 64) {
        sm[OFF_EMBW + tid]    = emb_W[tid];
        sm[OFF_B1 + tid]      = mh_b1[tid];
        sm[OFF_B1 + 64 + tid] = ch_b1[tid];
    }
    if (tid < 4)  sm[OFF_B2 + tid] = mh_b2[tid];
    if (tid < 10) sm[OFF_B2 + 4 + tid] = ch_b2[tid];

    // h0 = 0 in buffer 0 (dup layout); x[:,0,:] into Xs buffer 0
    for (int i = tid; i < 4096; i += NT) sm[OFF_HD + i] = 0.f;
    {
        int row = tid >> 4, k = tid & 15;   // 512 = 32 rows x 16 k
        float v = x[((size_t)(b0 + row) * SRC_LEN + 0) * IN_DIM + k];
        *reinterpret_cast<float2*>(&sm[OFF_XS + k * 64 + row * 2]) = make_float2(v, v);
    }
    __syncthreads();

    const int rg = tid & 15, jg = tid >> 4;
    const int j0 = 2 * jg;

    // encoder biases packed into accumulator seeds (loop-invariant)
    u64 bp[4];
    bp[0] = pack2(sm[OFF_EBIH + j0]      + sm[OFF_EBHH + j0],
                  sm[OFF_EBIH + j0 + 1]  + sm[OFF_EBHH + j0 + 1]);
    bp[1] = pack2(sm[OFF_EBIH + 64 + j0] + sm[OFF_EBHH + 64 + j0],
                  sm[OFF_EBIH + 65 + j0] + sm[OFF_EBHH + 65 + j0]);
    bp[2] = pack2(sm[OFF_EBIH + 128 + j0], sm[OFF_EBIH + 129 + j0]);
    bp[3] = pack2(sm[OFF_EBHH + 128 + j0], sm[OFF_EBHH + 129 + j0]);

    // ============ encoder: 1 barrier per step (h and x double-buffered) =====
    const int pr = tid >> 4, pk = tid & 15;   // prefetch assignment: 1 elt/thread
    for (int t = 0; t < SRC_LEN; ++t) {
        const int cur = t & 1, nxt = cur ^ 1;
        float pf = 0.f;
        if (t + 1 < SRC_LEN)
            pf = x[((size_t)(b0 + pr) * SRC_LEN + t + 1) * IN_DIM + pk];
        float hnew[2][2];
        gru_step(sm + OFF_EWIH, sm + OFF_EWHH,
                 sm + OFF_XS + cur * 1024, sm + OFF_HD + cur * 4096,
                 bp, rg, jg, hnew);
        store_h_dup(sm + OFF_HD + nxt * 4096, rg, j0, hnew);
        if (t + 1 < SRC_LEN)
            *reinterpret_cast<float2*>(&sm[OFF_XS + nxt * 1024 + pk * 64 + pr * 2]) = make_float2(pf, pf);
        __syncthreads();
    }
    // 128 encoder steps: final h lands in buffer 0; decoder t=0 reads cur=0. ✓

    // ====== decoder init: init_in = trg @ emb_W^T + emb_b (into Xs[0]) ======
    {
        int row = tid & 31, k = tid >> 5;   // 512 = 32 rows x 16 k
        float acc = sm[OFF_EMBB + k];
#pragma unroll
        for (int s = 0; s < 4; ++s)
            acc += trg[(size_t)(b0 + row) * 4 + s] * sm[OFF_EMBW + k * 4 + s];
        *reinterpret_cast<float2*>(&sm[OFF_XS + k * 64 + row * 2]) = make_float2(acc, acc);
    }
    // decoder biases packed
    bp[0] = pack2(sm[OFF_DBIH + j0]      + sm[OFF_DBHH + j0],
                  sm[OFF_DBIH + j0 + 1]  + sm[OFF_DBHH + j0 + 1]);
    bp[1] = pack2(sm[OFF_DBIH + 64 + j0] + sm[OFF_DBHH + 64 + j0],
                  sm[OFF_DBIH + 65 + j0] + sm[OFF_DBHH + 65 + j0]);
    bp[2] = pack2(sm[OFF_DBIH + 128 + j0], sm[OFF_DBIH + 129 + j0]);
    bp[3] = pack2(sm[OFF_DBHH + 128 + j0], sm[OFF_DBHH + 129 + j0]);
    __syncthreads();

    float* means = d_out;                                   // [B][SEQ][4]
    float* covs  = d_out + (size_t)B_TOT * SEQ * 4;         // [B][SEQ][10]
    float* sHrow = sm + OFF_HROW;
    float* sOrow = sm + OFF_OROW;
    float* sHH   = sm + OFF_HH;

    // ============ decoder: 3 barriers per step =============================
    for (int t = 0; t < SEQ; ++t) {
        const int cur = t & 1, nxt = cur ^ 1;

        // phase 1: GRU; write h[nxt] (dup, next GRU) + Hrow (row-major, out layer)
        float hnew[2][2];
        gru_step(sm + OFF_DWIH, sm + OFF_DWHH,
                 sm + OFF_XS + cur * 1024, sm + OFF_HD + cur * 4096,
                 bp, rg, jg, hnew);
        store_h_dup(sm + OFF_HD + nxt * 4096, rg, j0, hnew);
        {
            int row0 = 2 * rg, row1 = 2 * rg + 1;
            *reinterpret_cast<float2*>(&sHrow[row0 * HROW_S + j0])
                = make_float2(hnew[0][0], hnew[0][1]);
            *reinterpret_cast<float2*>(&sHrow[row1 * HROW_S + j0])
                = make_float2(hnew[1][0], hnew[1][1]);
        }
        __syncthreads();   // BAR1

        // phase 2: o = h @ out_W^T + out_b (LDS.128 pairs); 1 item/thread
        {
            int row = tid & 31, j = tid >> 5;   // j in 0..15
            u64 acc2 = dot_q<16>(sHrow + row * HROW_S, sm + OFF_OUTW + j * HD, 0ull);
            float2 a = unpack2(acc2);
            float o = a.x + a.y + sm[OFF_OUTB + j];
            *reinterpret_cast<float2*>(&sm[OFF_XS + nxt * 1024 + j * 64 + row * 2]) = make_float2(o, o);
            sOrow[row * OROW_S + j] = o;
        }
        __syncthreads();   // BAR2

        // phase 3: heads first layer + exact GELU. row = tid&31 is CONSTANT
        // across the 8 items/thread (512 ≡ 0 mod 32), so hoist this row's 16
        // o-values into registers ONCE (4 LDS.128) instead of reloading them
        // every iteration. u-assignment and fma2 order identical to before.
        {
            int row = tid & 31, w = tid >> 5;   // w in 0..15
            const float* orow = sOrow + row * OROW_S;
            u64 ov[8];
#pragma unroll
            for (int i = 0; i < 8; i += 2) {
                ulonglong2 q2 = *reinterpret_cast<const ulonglong2*>(orow + 2 * i);
                ov[i] = q2.x; ov[i + 1] = q2.y;
            }
#pragma unroll
            for (int q = 0; q < 8; ++q) {
                int u = q * 16 + w;             // u in 0..127
                const float* w1 = sm + OFF_W1 + u * 16;
                u64 acc2 = 0ull;
#pragma unroll
                for (int i = 0; i < 8; i += 2) {
                    ulonglong2 wv = *reinterpret_cast<const ulonglong2*>(w1 + 2 * i);
                    acc2 = fma2(ov[i], wv.x, acc2);
                    acc2 = fma2(ov[i + 1], wv.y, acc2);
                }
                float2 a = unpack2(acc2);
                float s = a.x + a.y + sm[OFF_B1 + u];
                sHH[row * HH_S + u] = 0.5f * s * (1.f + erff(s * 0.7071067811865475f));
            }
        }
        __syncthreads();   // BAR3

        // phase 4: heads second layer; 448 items, single pass; uniform W2/B2
        // indexing, LDS.128 operands; no trailing barrier — next-step sHH
        // writes are ordered behind BAR1'/BAR2'.
        if (tid < 448) {
            int row = tid & 31, v = tid >> 5;   // v in 0..13
            const float* hh = sHH + row * HH_S + ((v < 4) ? 0 : 64);
            u64 acc2 = dot_q<16>(hh, sm + OFF_W2 + v * 64, 0ull);
            float2 a = unpack2(acc2);
            float acc = a.x + a.y + sm[OFF_B2 + v];
            if (v < 4) {
                if (v >= 2) acc = fminf(fmaxf(acc, -1.f), 1.f);
                means[((size_t)(b0 + row) * SEQ + t) * 4 + v] = acc;
            } else {
                covs[((size_t)(b0 + row) * SEQ + t) * 10 + (v - 4)] = acc;
            }
        }
    }
}

extern "C" void kernel_launch(void* const* d_in, const int* in_sizes, int n_in,
                              void* d_out, int out_size)
{
    (void)in_sizes; (void)n_in; (void)out_size;
    cudaFuncSetAttribute(seq2seq_kernel,
                         cudaFuncAttributeMaxDynamicSharedMemorySize, SMEM_BYTES);
    seq2seq_kernel<<<B_TOT / ROWS, NT, SMEM_BYTES>>>(
        (const float*)d_in[0],  (const float*)d_in[1],
        (const float*)d_in[2],  (const float*)d_in[3],
        (const float*)d_in[4],  (const float*)d_in[5],
        (const float*)d_in[6],  (const float*)d_in[7],
        (const float*)d_in[8],  (const float*)d_in[9],
        (const float*)d_in[10], (const float*)d_in[11],
        (const float*)d_in[12], (const float*)d_in[13],
        (const float*)d_in[14], (const float*)d_in[15],
        (const float*)d_in[16], (const float*)d_in[17],
        (const float*)d_in[18], (const float*)d_in[19],
        (const float*)d_in[20], (const float*)d_in[21],
        (float*)d_out);
}

// round 12
// speedup vs baseline: 1.2184x; 1.2184x over previous
#include <cuda_runtime.h>
#include <math.h>

#define B_TOT   4096
#define SRC_LEN 128
#define IN_DIM  16
#define HD      64
#define G3      192
#define SEQ     100
#define ROWS    32
#define NT      512

typedef unsigned long long u64;

// packed fp32 FMA: d = a*b + c componentwise (Blackwell FFMA2 pipe, full fp32)
__device__ __forceinline__ u64 fma2(u64 a, u64 b, u64 c) {
    u64 d;
    asm("fma.rn.f32x2 %0, %1, %2, %3;" : "=l"(d) : "l"(a), "l"(b), "l"(c));
    return d;
}
__device__ __forceinline__ float2 unpack2(u64 v) {
    float2 f;
    asm("mov.b64 {%0, %1}, %2;" : "=f"(f.x), "=f"(f.y) : "l"(v));
    return f;
}
__device__ __forceinline__ u64 pack2(float lo, float hi) {
    u64 d;
    asm("mov.b64 %0, {%1, %2};" : "=l"(d) : "f"(lo), "f"(hi));
    return d;
}
__device__ __forceinline__ u64 ld64s(const float* p) {
    return *reinterpret_cast<const u64*>(p);
}
// fast gates. __fdividef returns 0 for |denominator| > 2^126, so exp-overflow
// saturates correctly: sigmoid -> 0, tanh -> 1 (and e->0 gives tanh -> -1).
__device__ __forceinline__ float sigm(float s) {
    return __fdividef(1.f, 1.f + __expf(-s));
}
__device__ __forceinline__ float tanh_fast(float x) {
    float e = __expf(2.f * x);
    return 1.f - __fdividef(2.f, e + 1.f);
}
// packed dot-product accumulate over n pair-of-pairs (4 floats per iter),
// both pointers 16B-aligned; accumulation order identical to the scalar-pair loop
template<int NQ>
__device__ __forceinline__ u64 dot_q(const float* __restrict__ a,
                                     const float* __restrict__ b, u64 acc2)
{
#pragma unroll
    for (int i = 0; i < NQ; ++i) {
        ulonglong2 av = *reinterpret_cast<const ulonglong2*>(a + 4 * i);
        ulonglong2 bv = *reinterpret_cast<const ulonglong2*>(b + 4 * i);
        acc2 = fma2(av.x, bv.x, acc2);
        acc2 = fma2(av.y, bv.y, acc2);
    }
    return acc2;
}

// ---- shared memory layout (float offsets) ----
// GRU weights, gate-pair-packed:
//   Wrz[k][pair][4] = {wr(2p), wr(2p+1), wz(2p), wz(2p+1)}  -> one LDS.128
//   Wn [k][pair][2] = {wn(2p), wn(2p+1)}                    -> one LDS.64
#define OFF_EWRZI 0       // [16][32][4] enc Wih r/z packed   (2048)
#define OFF_EWNI  2048    // [16][32][2] enc Wih n            (1024)
#define OFF_EWRZH 3072    // [64][32][4] enc Whh r/z packed   (8192)
#define OFF_EWNH  11264   // [64][32][2] enc Whh n            (4096)
#define OFF_DWRZI 15360   // dec Wih r/z                      (2048)
#define OFF_DWNI  17408   // dec Wih n                        (1024)
#define OFF_DWRZH 18432   // dec Whh r/z                      (8192)
#define OFF_DWNH  26624   // dec Whh n                        (4096)
#define OFF_EBIH 30720    // [192]
#define OFF_EBHH 30912
#define OFF_DBIH 31104
#define OFF_DBHH 31296
#define OFF_OUTW 31488    // [16][64]  (16B-aligned rows)
#define OFF_OUTB 32512    // [16]
#define OFF_EMBW 32528    // [16][4]
#define OFF_EMBB 32592    // [16]
#define OFF_W1   32608    // [128][16]  rows 0..63 = mean head, 64..127 = cov head
#define OFF_B1   34656    // [128]
#define OFF_W2   34784    // [14][64]   rows 0..3 = mean head, 4..13 = cov head
#define OFF_B2   35680    // [14] (ends 35694, pad 2)
#define OFF_HD   35696    // 2 x [64][32] h, k-major, double-buffered (4096)
#define OFF_XS   39792    // 2 x [16][32] input, k-major              (1024)
#define OFF_HROW 40816    // [32][68] h row-major, 16B-aligned rows   (2176)
#define OFF_OROW 42992    // [32][20] o row-major, 16B-aligned rows   (640)
#define OFF_HH   43632    // [32][132] head hidden, 16B-aligned rows  (4224)
#define SMEM_FLOATS 47856
#define SMEM_BYTES  (SMEM_FLOATS * 4)

#define HROW_S 68
#define OROW_S 20
#define HH_S   132

// Fused GRU matmul + gate, all in registers. 512-thread tiling:
// rows {2rg, 2rg+1} (rg = tid&15): one LDS.64 per activation per k.
// Hidden-unit pair = jg (tid>>4); j0 = 2*jg.
// Per k: 1 act LDS.64 + 1 weight LDS.128 (r+z pairs) + 1 weight LDS.64 (n)
// = 3 LDS (was 4). fma2 operand values/order identical to the 3-LDS.64
// version => bitwise-same results.
// Accumulators SEEDED with packed biases (bp[0]=b_r, bp[1]=b_z combined
// ih+hh pairs; bp[2]=b_in, bp[3]=b_hn).
// Reads h/x from CURRENT buffers only; caller writes NEXT buffers
// (double-buffered => no barrier inside the step).
__device__ __forceinline__ void gru_step(
    const float* __restrict__ Wrzi, const float* __restrict__ Wni,
    const float* __restrict__ Wrzh, const float* __restrict__ Wnh,
    const float* __restrict__ Xd,   const float* __restrict__ Hd,
    const u64* __restrict__ bp,
    int rg, int jg, float hnew[2][2])
{
    u64 ir[2], iz[2], inn[2], hr[2], hz[2], hn[2];
#pragma unroll
    for (int r = 0; r < 2; ++r) {
        ir[r] = bp[0]; iz[r] = bp[1]; inn[r] = bp[2]; hn[r] = bp[3];
        hr[r] = 0ull;  hz[r] = 0ull;
    }
    const int j0  = 2 * jg;
    const int ro2 = 2 * rg;   // float offset of rows {2rg, 2rg+1}
    const int p4  = 4 * jg;   // Wrz slot offset
    const int p2  = 2 * jg;   // Wn slot offset

#pragma unroll 4
    for (int k = 0; k < IN_DIM; ++k) {
        float2 xf = *reinterpret_cast<const float2*>(&Xd[k * 32 + ro2]);
        u64 x0 = pack2(xf.x, xf.x), x1 = pack2(xf.y, xf.y);
        ulonglong2 wq = *reinterpret_cast<const ulonglong2*>(&Wrzi[k * 128 + p4]);
        u64 wn_ = ld64s(&Wni[k * 64 + p2]);
        ir[0]  = fma2(x0, wq.x, ir[0]);   ir[1]  = fma2(x1, wq.x, ir[1]);
        iz[0]  = fma2(x0, wq.y, iz[0]);   iz[1]  = fma2(x1, wq.y, iz[1]);
        inn[0] = fma2(x0, wn_, inn[0]);   inn[1] = fma2(x1, wn_, inn[1]);
    }

#pragma unroll 8
    for (int k = 0; k < HD; ++k) {
        float2 hf = *reinterpret_cast<const float2*>(&Hd[k * 32 + ro2]);
        u64 h0 = pack2(hf.x, hf.x), h1 = pack2(hf.y, hf.y);
        ulonglong2 wq = *reinterpret_cast<const ulonglong2*>(&Wrzh[k * 128 + p4]);
        u64 wn_ = ld64s(&Wnh[k * 64 + p2]);
        hr[0] = fma2(h0, wq.x, hr[0]);    hr[1] = fma2(h1, wq.x, hr[1]);
        hz[0] = fma2(h0, wq.y, hz[0]);    hz[1] = fma2(h1, wq.y, hz[1]);
        hn[0] = fma2(h0, wn_, hn[0]);     hn[1] = fma2(h1, wn_, hn[1]);
    }

    // old h for units j0, j0+1 at both rows: one LDS.64 per unit
    float2 f0 = *reinterpret_cast<const float2*>(&Hd[j0 * 32 + ro2]);
    float2 f1 = *reinterpret_cast<const float2*>(&Hd[(j0 + 1) * 32 + ro2]);
    float holdv[2][2] = { {f0.x, f1.x}, {f0.y, f1.y} };

#pragma unroll
    for (int r = 0; r < 2; ++r) {
        float2 fir = unpack2(ir[r]),  fiz = unpack2(iz[r]),  fin = unpack2(inn[r]);
        float2 fhr = unpack2(hr[r]),  fhz = unpack2(hz[r]),  fhn = unpack2(hn[r]);
#pragma unroll
        for (int h = 0; h < 2; ++h) {
            float vir = h ? fir.y : fir.x, vhr = h ? fhr.y : fhr.x;
            float viz = h ? fiz.y : fiz.x, vhz = h ? fhz.y : fhz.x;
            float vin = h ? fin.y : fin.x, vhn = h ? fhn.y : fhn.x;
            float rr = sigm(vir + vhr);                  // biases pre-seeded
            float zz = sigm(viz + vhz);
            float nn = tanh_fast(vin + rr * vhn);
            hnew[r][h] = (1.f - zz) * nn + zz * holdv[r][h];
        }
    }
}

// store hnew into the k-major NEXT buffer: one STS.64 per unit
__device__ __forceinline__ void store_h(
    float* __restrict__ hdn, int rg, int j0, const float hnew[2][2])
{
    const int ro2 = 2 * rg;
    *reinterpret_cast<float2*>(&hdn[j0 * 32 + ro2])
        = make_float2(hnew[0][0], hnew[1][0]);
    *reinterpret_cast<float2*>(&hdn[(j0 + 1) * 32 + ro2])
        = make_float2(hnew[0][1], hnew[1][1]);
}

__global__ void __launch_bounds__(NT)
seq2seq_kernel(
    const float* __restrict__ x,       const float* __restrict__ trg,
    const float* __restrict__ enc_Wih, const float* __restrict__ enc_bih,
    const float* __restrict__ enc_Whh, const float* __restrict__ enc_bhh,
    const float* __restrict__ dec_Wih, const float* __restrict__ dec_bih,
    const float* __restrict__ dec_Whh, const float* __restrict__ dec_bhh,
    const float* __restrict__ out_W,   const float* __restrict__ out_b,
    const float* __restrict__ emb_W,   const float* __restrict__ emb_b,
    const float* __restrict__ mh_W1,   const float* __restrict__ mh_b1,
    const float* __restrict__ mh_W2,   const float* __restrict__ mh_b2,
    const float* __restrict__ ch_W1,   const float* __restrict__ ch_b1,
    const float* __restrict__ ch_W2,   const float* __restrict__ ch_b2,
    float* __restrict__ d_out)
{
    extern __shared__ float sm[];
    const int tid = threadIdx.x;
    const int b0  = blockIdx.x * ROWS;

    // ---- load + repack weights into smem (gate-pair-packed layout) ----
    // Wih: i = g*16 + k, g in 0..191. Gates: g<64 -> r(j=g), <128 -> z, else n.
    for (int i = tid; i < 3072; i += NT) {
        int g = i >> 4, k = i & 15;
        if (g < 128) {
            int gate = g >> 6, j = g & 63;
            int dst = k * 128 + ((j >> 1) << 2) + (gate << 1) + (j & 1);
            sm[OFF_EWRZI + dst] = enc_Wih[i];
            sm[OFF_DWRZI + dst] = dec_Wih[i];
        } else {
            int j = g - 128;
            int dst = k * 64 + j;
            sm[OFF_EWNI + dst] = enc_Wih[i];
            sm[OFF_DWNI + dst] = dec_Wih[i];
        }
    }
    // Whh: i = g*64 + k
    for (int i = tid; i < 12288; i += NT) {
        int g = i >> 6, k = i & 63;
        if (g < 128) {
            int gate = g >> 6, j = g & 63;
            int dst = k * 128 + ((j >> 1) << 2) + (gate << 1) + (j & 1);
            sm[OFF_EWRZH + dst] = enc_Whh[i];
            sm[OFF_DWRZH + dst] = dec_Whh[i];
        } else {
            int j = g - 128;
            int dst = k * 64 + j;
            sm[OFF_EWNH + dst] = enc_Whh[i];
            sm[OFF_DWNH + dst] = dec_Whh[i];
        }
    }
    for (int i = tid; i < G3; i += NT) {
        sm[OFF_EBIH + i] = enc_bih[i];
        sm[OFF_EBHH + i] = enc_bhh[i];
        sm[OFF_DBIH + i] = dec_bih[i];
        sm[OFF_DBHH + i] = dec_bhh[i];
    }
    // head weights combined: W1 = [mh_W1 ; ch_W1], W2 = [mh_W2 ; ch_W2]
    for (int i = tid; i < 1024; i += NT) {
        sm[OFF_OUTW + i]      = out_W[i];
        sm[OFF_W1 + i]        = mh_W1[i];
        sm[OFF_W1 + 1024 + i] = ch_W1[i];
    }
    for (int i = tid; i < 640; i += NT) sm[OFF_W2 + 256 + i] = ch_W2[i];
    for (int i = tid; i < 256; i += NT) sm[OFF_W2 + i] = mh_W2[i];
    if (tid < 16) { sm[OFF_OUTB + tid] = out_b[tid]; sm[OFF_EMBB + tid] = emb_b[tid]; }
    if (tid < 64) {
        sm[OFF_EMBW + tid]    = emb_W[tid];
        sm[OFF_B1 + tid]      = mh_b1[tid];
        sm[OFF_B1 + 64 + tid] = ch_b1[tid];
    }
    if (tid < 4)  sm[OFF_B2 + tid] = mh_b2[tid];
    if (tid < 10) sm[OFF_B2 + 4 + tid] = ch_b2[tid];

    // h0 = 0 in both buffers; x[:,0,:] into Xs buffer 0 (k-major scalar)
    for (int i = tid; i < 4096; i += NT) sm[OFF_HD + i] = 0.f;
    {
        int row = tid & 31, k = tid >> 5;   // 512 = 32 rows x 16 k
        sm[OFF_XS + k * 32 + row] =
            x[((size_t)(b0 + row) * SRC_LEN + 0) * IN_DIM + k];
    }
    __syncthreads();

    const int rg = tid & 15, jg = tid >> 4;
    const int j0 = 2 * jg;

    // encoder biases packed into accumulator seeds (loop-invariant)
    u64 bp[4];
    bp[0] = pack2(sm[OFF_EBIH + j0]      + sm[OFF_EBHH + j0],
                  sm[OFF_EBIH + j0 + 1]  + sm[OFF_EBHH + j0 + 1]);
    bp[1] = pack2(sm[OFF_EBIH + 64 + j0] + sm[OFF_EBHH + 64 + j0],
                  sm[OFF_EBIH + 65 + j0] + sm[OFF_EBHH + 65 + j0]);
    bp[2] = pack2(sm[OFF_EBIH + 128 + j0], sm[OFF_EBIH + 129 + j0]);
    bp[3] = pack2(sm[OFF_EBHH + 128 + j0], sm[OFF_EBHH + 129 + j0]);

    // ============ encoder: 1 barrier per step (h and x double-buffered) =====
    // prefetch map: row=tid&31, k=tid>>5 => per-warp store is 128B contiguous
    const int pr = tid & 31, pk = tid >> 5;
    for (int t = 0; t < SRC_LEN; ++t) {
        const int cur = t & 1, nxt = cur ^ 1;
        float pf = 0.f;
        if (t + 1 < SRC_LEN)
            pf = x[((size_t)(b0 + pr) * SRC_LEN + t + 1) * IN_DIM + pk];
        float hnew[2][2];
        gru_step(sm + OFF_EWRZI, sm + OFF_EWNI, sm + OFF_EWRZH, sm + OFF_EWNH,
                 sm + OFF_XS + cur * 512, sm + OFF_HD + cur * 2048,
                 bp, rg, jg, hnew);
        store_h(sm + OFF_HD + nxt * 2048, rg, j0, hnew);
        if (t + 1 < SRC_LEN)
            sm[OFF_XS + nxt * 512 + pk * 32 + pr] = pf;
        __syncthreads();
    }
    // 128 encoder steps: final h lands in buffer 0; decoder t=0 reads cur=0. ✓

    // ====== decoder init: init_in = trg @ emb_W^T + emb_b (into Xs[0]) ======
    {
        int row = tid & 31, k = tid >> 5;   // 512 = 32 rows x 16 k
        float acc = sm[OFF_EMBB + k];
#pragma unroll
        for (int s = 0; s < 4; ++s)
            acc += trg[(size_t)(b0 + row) * 4 + s] * sm[OFF_EMBW + k * 4 + s];
        sm[OFF_XS + k * 32 + row] = acc;
    }
    // decoder biases packed
    bp[0] = pack2(sm[OFF_DBIH + j0]      + sm[OFF_DBHH + j0],
                  sm[OFF_DBIH + j0 + 1]  + sm[OFF_DBHH + j0 + 1]);
    bp[1] = pack2(sm[OFF_DBIH + 64 + j0] + sm[OFF_DBHH + 64 + j0],
                  sm[OFF_DBIH + 65 + j0] + sm[OFF_DBHH + 65 + j0]);
    bp[2] = pack2(sm[OFF_DBIH + 128 + j0], sm[OFF_DBIH + 129 + j0]);
    bp[3] = pack2(sm[OFF_DBHH + 128 + j0], sm[OFF_DBHH + 129 + j0]);
    __syncthreads();

    float* means = d_out;                                   // [B][SEQ][4]
    float* covs  = d_out + (size_t)B_TOT * SEQ * 4;         // [B][SEQ][10]
    float* sHrow = sm + OFF_HROW;
    float* sOrow = sm + OFF_OROW;
    float* sHH   = sm + OFF_HH;

    // ============ decoder: 3 barriers per step =============================
    for (int t = 0; t < SEQ; ++t) {
        const int cur = t & 1, nxt = cur ^ 1;

        // phase 1: GRU; write h[nxt] (k-major, next GRU) + Hrow (row-major)
        float hnew[2][2];
        gru_step(sm + OFF_DWRZI, sm + OFF_DWNI, sm + OFF_DWRZH, sm + OFF_DWNH,
                 sm + OFF_XS + cur * 512, sm + OFF_HD + cur * 2048,
                 bp, rg, jg, hnew);
        store_h(sm + OFF_HD + nxt * 2048, rg, j0, hnew);
        {
            int row0 = 2 * rg, row1 = 2 * rg + 1;
            *reinterpret_cast<float2*>(&sHrow[row0 * HROW_S + j0])
                = make_float2(hnew[0][0], hnew[0][1]);
            *reinterpret_cast<float2*>(&sHrow[row1 * HROW_S + j0])
                = make_float2(hnew[1][0], hnew[1][1]);
        }
        __syncthreads();   // BAR1

        // phase 2: o = h @ out_W^T + out_b (LDS.128 pairs); 1 item/thread
        {
            int row = tid & 31, j = tid >> 5;   // j in 0..15
            u64 acc2 = dot_q<16>(sHrow + row * HROW_S, sm + OFF_OUTW + j * HD, 0ull);
            float2 a = unpack2(acc2);
            float o = a.x + a.y + sm[OFF_OUTB + j];
            sm[OFF_XS + nxt * 512 + j * 32 + row] = o;   // k-major next input
            sOrow[row * OROW_S + j] = o;
        }
        __syncthreads();   // BAR2

        // phase 3: heads first layer + exact GELU. row = tid&31 is CONSTANT
        // across the 8 items/thread, so hoist this row's 16 o-values into
        // registers once (4 LDS.128); weights broadcast per warp.
        {
            int row = tid & 31, w = tid >> 5;   // w in 0..15
            const float* orow = sOrow + row * OROW_S;
            u64 ov[8];
#pragma unroll
            for (int i = 0; i < 8; i += 2) {
                ulonglong2 q2 = *reinterpret_cast<const ulonglong2*>(orow + 2 * i);
                ov[i] = q2.x; ov[i + 1] = q2.y;
            }
#pragma unroll
            for (int q = 0; q < 8; ++q) {
                int u = q * 16 + w;             // u in 0..127
                const float* w1 = sm + OFF_W1 + u * 16;
                u64 acc2 = 0ull;
#pragma unroll
                for (int i = 0; i < 8; i += 2) {
                    ulonglong2 wv = *reinterpret_cast<const ulonglong2*>(w1 + 2 * i);
                    acc2 = fma2(ov[i], wv.x, acc2);
                    acc2 = fma2(ov[i + 1], wv.y, acc2);
                }
                float2 a = unpack2(acc2);
                float s = a.x + a.y + sm[OFF_B1 + u];
                sHH[row * HH_S + u] = 0.5f * s * (1.f + erff(s * 0.7071067811865475f));
            }
        }
        __syncthreads();   // BAR3

        // phase 4: heads second layer; 448 items, single pass; uniform W2/B2
        // indexing, LDS.128 operands; no trailing barrier — next-step sHH
        // writes are ordered behind BAR1'/BAR2'.
        if (tid < 448) {
            int row = tid & 31, v = tid >> 5;   // v in 0..13
            const float* hh = sHH + row * HH_S + ((v < 4) ? 0 : 64);
            u64 acc2 = dot_q<16>(hh, sm + OFF_W2 + v * 64, 0ull);
            float2 a = unpack2(acc2);
            float acc = a.x + a.y + sm[OFF_B2 + v];
            if (v < 4) {
                if (v >= 2) acc = fminf(fmaxf(acc, -1.f), 1.f);
                means[((size_t)(b0 + row) * SEQ + t) * 4 + v] = acc;
            } else {
                covs[((size_t)(b0 + row) * SEQ + t) * 10 + (v - 4)] = acc;
            }
        }
    }
}

extern "C" void kernel_launch(void* const* d_in, const int* in_sizes, int n_in,
                              void* d_out, int out_size)
{
    (void)in_sizes; (void)n_in; (void)out_size;
    cudaFuncSetAttribute(seq2seq_kernel,
                         cudaFuncAttributeMaxDynamicSharedMemorySize, SMEM_BYTES);
    seq2seq_kernel<<<B_TOT / ROWS, NT, SMEM_BYTES>>>(
        (const float*)d_in[0],  (const float*)d_in[1],
        (const float*)d_in[2],  (const float*)d_in[3],
        (const float*)d_in[4],  (const float*)d_in[5],
        (const float*)d_in[6],  (const float*)d_in[7],
        (const float*)d_in[8],  (const float*)d_in[9],
        (const float*)d_in[10], (const float*)d_in[11],
        (const float*)d_in[12], (const float*)d_in[13],
        (const float*)d_in[14], (const float*)d_in[15],
        (const float*)d_in[16], (const float*)d_in[17],
        (const float*)d_in[18], (const float*)d_in[19],
        (const float*)d_in[20], (const float*)d_in[21],
        (float*)d_out);
}